// round 1
// baseline (speedup 1.0000x reference)
#include <cuda_runtime.h>

#define Bb 8
#define Nn 4096
#define Mm 1024
#define Dd 64
#define DOUT 128

// Scratch (device globals — no allocation allowed)
__device__ float g_q[Bb*Nn*Dd];      // [b][n][d]
__device__ float g_kT[Bb*Dd*Mm];     // [b][d][m]  (k transposed)
__device__ float g_v[Bb*Mm*Dd];      // [b][m][d]
__device__ float g_kern[Bb*Nn*Dd];   // [b][n][d]

// ---------------------------------------------------------------------------
// Projection GEMM: C[r][e] = sum_d A[r][d] * W[d][e], 64 rows per block.
// Optionally writes C transposed per-batch ([b][e][m]) for the K matrix.
// ---------------------------------------------------------------------------
__global__ __launch_bounds__(256) void proj_kernel(
    const float* __restrict__ A, const float* __restrict__ W,
    float* __restrict__ C, int transposed, int rows_per_batch)
{
    __shared__ float sA[64*64];   // xor-swizzled on float4 blocks
    __shared__ float sW[64*64];   // plain row-major
    int tid = threadIdx.x;
    int rowbase = blockIdx.x * 64;

#pragma unroll
    for (int p = 0; p < 4; p++) {
        int lin = tid + 256*p;
        int r = lin >> 4, c4 = lin & 15;
        float4 av = *(const float4*)(A + (rowbase + r)*64 + c4*4);
        *(float4*)(sA + r*64 + ((c4 ^ (r & 15)) << 2)) = av;
        *(float4*)(sW + r*64 + (c4 << 2)) = *(const float4*)(W + r*64 + c4*4);
    }
    __syncthreads();

    int ty = tid >> 4, tx = tid & 15;
    int r0 = ty*4, c0 = tx*4;
    int rx[4], rb[4];
#pragma unroll
    for (int i = 0; i < 4; i++) { rx[i] = (r0+i) & 15; rb[i] = (r0+i)*64; }

    float acc[4][4] = {};
#pragma unroll
    for (int d4 = 0; d4 < 16; d4++) {
        float a[4][4], bb[4][4];
#pragma unroll
        for (int i = 0; i < 4; i++) {
            float4 t = *(const float4*)(sA + rb[i] + ((d4 ^ rx[i]) << 2));
            a[i][0]=t.x; a[i][1]=t.y; a[i][2]=t.z; a[i][3]=t.w;
        }
#pragma unroll
        for (int k = 0; k < 4; k++) {
            float4 t = *(const float4*)(sW + (d4*4+k)*64 + c0);
            bb[k][0]=t.x; bb[k][1]=t.y; bb[k][2]=t.z; bb[k][3]=t.w;
        }
#pragma unroll
        for (int k = 0; k < 4; k++)
#pragma unroll
            for (int i = 0; i < 4; i++)
#pragma unroll
                for (int j = 0; j < 4; j++)
                    acc[i][j] = fmaf(a[i][k], bb[k][j], acc[i][j]);
    }

    if (!transposed) {
#pragma unroll
        for (int i = 0; i < 4; i++) {
            float4 o = make_float4(acc[i][0], acc[i][1], acc[i][2], acc[i][3]);
            *(float4*)(C + (rowbase + r0 + i)*64 + c0) = o;
        }
    } else {
#pragma unroll
        for (int i = 0; i < 4; i++) {
            int grow = rowbase + r0 + i;
            int b = grow / rows_per_batch;
            int rl = grow - b*rows_per_batch;
#pragma unroll
            for (int j = 0; j < 4; j++)
                C[(b*64 + c0 + j)*rows_per_batch + rl] = acc[i][j];
        }
    }
}

// ---------------------------------------------------------------------------
// Fused bi-kernel attention (flash-style, single pass, no running max):
//   num[n][d] += w1(n,m) * exp(s[n][m]) * v[m][d];  den[n] += exp(s[n][m])
// 64 queries x 64 keys per tile, 16 key-tiles looped.
// ---------------------------------------------------------------------------
__global__ __launch_bounds__(256, 2) void attn_kernel(
    const float* __restrict__ xyz1, const float* __restrict__ xyz2,
    const float* __restrict__ gammap)
{
    extern __shared__ float sm[];
    float* sQ  = sm;           // [64][64] swizzled
    float* sK  = sm + 4096;    // kT: [d][m] plain
    float* sV  = sm + 8192;    // [m][d] plain
    float* sP  = sm + 12288;   // [64 rows][64 m] swizzled
    float* sX2 = sm + 16384;   // [64][3]

    int tid = threadIdx.x;
    int bI = blockIdx.y;
    int nbase = blockIdx.x * 64;
    float g = gammap[0];

    const float* qsrc = g_q + (bI*Nn + nbase)*64;
#pragma unroll
    for (int p = 0; p < 4; p++) {
        int lin = tid + 256*p;
        int r = lin >> 4, c4 = lin & 15;
        float4 t = *(const float4*)(qsrc + r*64 + c4*4);
        *(float4*)(sQ + r*64 + ((c4 ^ (r & 15)) << 2)) = t;
    }

    int ty = tid >> 4, tx = tid & 15;
    int r0 = ty*4, c0 = tx*4;
    int rx[4], rb[4];
#pragma unroll
    for (int i = 0; i < 4; i++) { rx[i] = (r0+i) & 15; rb[i] = (r0+i)*64; }

    float x1x[4], x1y[4], x1z[4];
#pragma unroll
    for (int i = 0; i < 4; i++) {
        const float* xp = xyz1 + (bI*Nn + nbase + r0 + i)*3;
        x1x[i] = xp[0]; x1y[i] = xp[1]; x1z[i] = xp[2];
    }

    const float* ksrc  = g_kT + bI*64*Mm;
    const float* vsrc  = g_v  + bI*Mm*64;
    const float* x2src = xyz2 + bI*Mm*3;

    float acc[4][4] = {};
    float dsum[4] = {};

    for (int mt = 0; mt < 16; mt++) {
        int mbase = mt*64;
        __syncthreads();  // prev PV reads of sP/sV done; safe to overwrite
#pragma unroll
        for (int p = 0; p < 4; p++) {
            int lin = tid + 256*p;
            int r = lin >> 4, c4 = lin & 15;
            *(float4*)(sK + r*64 + c4*4) = *(const float4*)(ksrc + r*Mm + mbase + c4*4);
            *(float4*)(sV + r*64 + c4*4) = *(const float4*)(vsrc + (mbase + r)*64 + c4*4);
        }
        if (tid < 192) sX2[tid] = x2src[mbase*3 + tid];
        __syncthreads();

        // S = q . k^T  (4x4 microtile)
        float s[4][4] = {};
#pragma unroll
        for (int d4 = 0; d4 < 16; d4++) {
            float a[4][4], bb[4][4];
#pragma unroll
            for (int i = 0; i < 4; i++) {
                float4 t = *(const float4*)(sQ + rb[i] + ((d4 ^ rx[i]) << 2));
                a[i][0]=t.x; a[i][1]=t.y; a[i][2]=t.z; a[i][3]=t.w;
            }
#pragma unroll
            for (int k = 0; k < 4; k++) {
                float4 t = *(const float4*)(sK + (d4*4+k)*64 + c0);
                bb[k][0]=t.x; bb[k][1]=t.y; bb[k][2]=t.z; bb[k][3]=t.w;
            }
#pragma unroll
            for (int k = 0; k < 4; k++)
#pragma unroll
                for (int i = 0; i < 4; i++)
#pragma unroll
                    for (int j = 0; j < 4; j++)
                        s[i][j] = fmaf(a[i][k], bb[k][j], s[i][j]);
        }

        // RBF weight + exp; write weighted P, accumulate raw-exp denominator
        float x2x[4], x2y[4], x2z[4];
#pragma unroll
        for (int j = 0; j < 4; j++) {
            x2x[j] = sX2[(c0+j)*3+0];
            x2y[j] = sX2[(c0+j)*3+1];
            x2z[j] = sX2[(c0+j)*3+2];
        }
#pragma unroll
        for (int i = 0; i < 4; i++) {
            float4 pw;
            float* pwp = (float*)&pw;
#pragma unroll
            for (int j = 0; j < 4; j++) {
                float e2 = __expf(s[i][j]);
                dsum[i] += e2;
                float dx = x1x[i] - x2x[j];
                float dy = x1y[i] - x2y[j];
                float dz = x1z[i] - x2z[j];
                float d2 = fmaf(dx, dx, fmaf(dy, dy, dz*dz));
                float e1 = __expf(-g * d2);
                float w  = (e1 > 0.05f) ? e1 : 0.0f;
                pwp[j] = w * e2;
            }
            *(float4*)(sP + rb[i] + ((tx ^ rx[i]) << 2)) = pw;
        }
        __syncthreads();

        // acc += P . V
#pragma unroll
        for (int m4 = 0; m4 < 16; m4++) {
            float a[4][4], bb[4][4];
#pragma unroll
            for (int i = 0; i < 4; i++) {
                float4 t = *(const float4*)(sP + rb[i] + ((m4 ^ rx[i]) << 2));
                a[i][0]=t.x; a[i][1]=t.y; a[i][2]=t.z; a[i][3]=t.w;
            }
#pragma unroll
            for (int k = 0; k < 4; k++) {
                float4 t = *(const float4*)(sV + (m4*4+k)*64 + c0);
                bb[k][0]=t.x; bb[k][1]=t.y; bb[k][2]=t.z; bb[k][3]=t.w;
            }
#pragma unroll
            for (int k = 0; k < 4; k++)
#pragma unroll
                for (int i = 0; i < 4; i++)
#pragma unroll
                    for (int j = 0; j < 4; j++)
                        acc[i][j] = fmaf(a[i][k], bb[k][j], acc[i][j]);
        }
    }

    // Row denominators: reduce across the 16 tx lanes sharing each row group
#pragma unroll
    for (int off = 1; off < 16; off <<= 1)
#pragma unroll
        for (int i = 0; i < 4; i++)
            dsum[i] += __shfl_xor_sync(0xFFFFFFFFu, dsum[i], off);

    float* kout = g_kern + (bI*Nn + nbase)*64;
#pragma unroll
    for (int i = 0; i < 4; i++) {
        float inv = 1.0f / dsum[i];
        float4 o = make_float4(acc[i][0]*inv, acc[i][1]*inv, acc[i][2]*inv, acc[i][3]*inv);
        *(float4*)(kout + (r0+i)*64 + c0) = o;
    }
}

// ---------------------------------------------------------------------------
// Output MLP: out = relu(concat(points1, kern) @ Wo + bo), K split 64|64.
// ---------------------------------------------------------------------------
__global__ __launch_bounds__(256) void mlp_kernel(
    const float* __restrict__ p1, const float* __restrict__ Wo,
    const float* __restrict__ bo, float* __restrict__ out)
{
    __shared__ float sA[64*64];    // swizzled
    __shared__ float sB[64*128];   // plain
    int tid = threadIdx.x;
    int rowbase = blockIdx.x * 64;
    int ty = tid >> 4, tx = tid & 15;
    int r0 = ty*4, c0 = tx*4;
    int rx[4], rb[4];
#pragma unroll
    for (int i = 0; i < 4; i++) { rx[i] = (r0+i) & 15; rb[i] = (r0+i)*64; }

    float acc[4][8] = {};
#pragma unroll 1
    for (int ch = 0; ch < 2; ch++) {
        const float* Asrc = ch ? (const float*)g_kern : p1;
        __syncthreads();
#pragma unroll
        for (int p = 0; p < 4; p++) {
            int lin = tid + 256*p;
            int r = lin >> 4, c4 = lin & 15;
            float4 t = *(const float4*)(Asrc + (rowbase + r)*64 + c4*4);
            *(float4*)(sA + r*64 + ((c4 ^ (r & 15)) << 2)) = t;
        }
#pragma unroll
        for (int p = 0; p < 8; p++) {
            int lin = tid + 256*p;           // 0..2047
            int r = lin >> 5, c4 = lin & 31;
            *(float4*)(sB + r*128 + c4*4) = *(const float4*)(Wo + (ch*64 + r)*128 + c4*4);
        }
        __syncthreads();

#pragma unroll
        for (int d4 = 0; d4 < 16; d4++) {
            float a[4][4], b1[4][4], b2[4][4];
#pragma unroll
            for (int i = 0; i < 4; i++) {
                float4 t = *(const float4*)(sA + rb[i] + ((d4 ^ rx[i]) << 2));
                a[i][0]=t.x; a[i][1]=t.y; a[i][2]=t.z; a[i][3]=t.w;
            }
#pragma unroll
            for (int k = 0; k < 4; k++) {
                float4 t = *(const float4*)(sB + (d4*4+k)*128 + c0);
                b1[k][0]=t.x; b1[k][1]=t.y; b1[k][2]=t.z; b1[k][3]=t.w;
                float4 u = *(const float4*)(sB + (d4*4+k)*128 + 64 + c0);
                b2[k][0]=u.x; b2[k][1]=u.y; b2[k][2]=u.z; b2[k][3]=u.w;
            }
#pragma unroll
            for (int k = 0; k < 4; k++)
#pragma unroll
                for (int i = 0; i < 4; i++) {
#pragma unroll
                    for (int j = 0; j < 4; j++) {
                        acc[i][j]   = fmaf(a[i][k], b1[k][j], acc[i][j]);
                        acc[i][4+j] = fmaf(a[i][k], b2[k][j], acc[i][4+j]);
                    }
                }
        }
    }

    float bov[8];
#pragma unroll
    for (int j = 0; j < 4; j++) { bov[j] = bo[c0+j]; bov[4+j] = bo[64+c0+j]; }
#pragma unroll
    for (int i = 0; i < 4; i++) {
        int grow = rowbase + r0 + i;
        float4 o1, o2;
        o1.x = fmaxf(acc[i][0]+bov[0], 0.0f);
        o1.y = fmaxf(acc[i][1]+bov[1], 0.0f);
        o1.z = fmaxf(acc[i][2]+bov[2], 0.0f);
        o1.w = fmaxf(acc[i][3]+bov[3], 0.0f);
        o2.x = fmaxf(acc[i][4]+bov[4], 0.0f);
        o2.y = fmaxf(acc[i][5]+bov[5], 0.0f);
        o2.z = fmaxf(acc[i][6]+bov[6], 0.0f);
        o2.w = fmaxf(acc[i][7]+bov[7], 0.0f);
        *(float4*)(out + grow*128 + c0) = o1;
        *(float4*)(out + grow*128 + 64 + c0) = o2;
    }
}

// ---------------------------------------------------------------------------
extern "C" void kernel_launch(void* const* d_in, const int* in_sizes, int n_in,
                              void* d_out, int out_size)
{
    const float* xyz1 = (const float*)d_in[0];
    const float* xyz2 = (const float*)d_in[1];
    const float* p1   = (const float*)d_in[2];
    const float* p2   = (const float*)d_in[3];
    const float* Wq   = (const float*)d_in[4];
    const float* Wk   = (const float*)d_in[5];
    const float* Wv   = (const float*)d_in[6];
    const float* gm   = (const float*)d_in[7];
    const float* Wo   = (const float*)d_in[8];
    const float* bo   = (const float*)d_in[9];
    float* out = (float*)d_out;

    float *dq, *dkT, *dv;
    cudaGetSymbolAddress((void**)&dq,  g_q);
    cudaGetSymbolAddress((void**)&dkT, g_kT);
    cudaGetSymbolAddress((void**)&dv,  g_v);

    // projections
    proj_kernel<<<(Bb*Nn)/64, 256>>>(p1, Wq, dq,  0, Nn);
    proj_kernel<<<(Bb*Mm)/64, 256>>>(p2, Wk, dkT, 1, Mm);
    proj_kernel<<<(Bb*Mm)/64, 256>>>(p2, Wv, dv,  0, Mm);

    // fused bi-kernel attention
    const int ATT_SMEM = (4*4096 + 192) * (int)sizeof(float);  // 66304 B
    cudaFuncSetAttribute(attn_kernel, cudaFuncAttributeMaxDynamicSharedMemorySize, ATT_SMEM);
    attn_kernel<<<dim3(Nn/64, Bb), 256, ATT_SMEM>>>(xyz1, xyz2, gm);

    // output MLP
    mlp_kernel<<<(Bb*Nn)/64, 256>>>(p1, Wo, bo, out);
}

// round 4
// speedup vs baseline: 1.9016x; 1.9016x over previous
#include <cuda_runtime.h>
#include <cstdint>

#define Bb 8
#define Nn 4096
#define Mm 1024

// ---------------------------------------------------------------------------
// Scratch (device globals) — all pre-swizzled images for flat bulk copies
// ---------------------------------------------------------------------------
__device__ float g_qh[Bb*Nn*64];    // Q hi, per-128-row-chunk swizzled images
__device__ float g_ql[Bb*Nn*64];    // Q lo
__device__ float g_kh[Bb*Mm*64];    // K hi, per-64-key-tile swizzled images ([key][d])
__device__ float g_kl[Bb*Mm*64];    // K lo
__device__ float g_vT[Bb*Mm*64];    // V^T, per-64-key-tile swizzled images ([d][key])
__device__ float g_kern[Bb*Nn*64];  // attention output [b][n][d]

// ---------------------------------------------------------------------------
// Helpers
// ---------------------------------------------------------------------------
__device__ __forceinline__ uint32_t smem_u32(const void* p) {
    uint32_t a;
    asm("{ .reg .u64 t; cvta.to.shared.u64 t, %1; cvt.u32.u64 %0, t; }" : "=r"(a) : "l"(p));
    return a;
}
__device__ __forceinline__ float tf32_rna(float x) {
    uint32_t u;
    asm("cvt.rna.tf32.f32 %0, %1;" : "=r"(u) : "f"(x));
    return __uint_as_float(u);
}

#define MBAR_INIT(a, c) asm volatile("mbarrier.init.shared.b64 [%0], %1;" :: "r"(a), "r"((uint32_t)(c)) : "memory")
#define MBAR_EXPECT(a, b) asm volatile("mbarrier.arrive.expect_tx.shared.b64 _, [%0], %1;" :: "r"(a), "r"((uint32_t)(b)) : "memory")
#define MBAR_WAIT(a, ph) do { \
    asm volatile("{ .reg .pred P1; WL_%=: mbarrier.try_wait.parity.acquire.cta.shared::cta.b64 P1, [%0], %1, 0x989680; @P1 bra.uni WD_%=; bra.uni WL_%=; WD_%=: }" \
        :: "r"(a), "r"((uint32_t)(ph)) : "memory"); } while (0)

__device__ __forceinline__ void bulk_cp(uint32_t dst, const void* src, uint32_t bytes, uint32_t mbar) {
    asm volatile("cp.async.bulk.shared::cta.global.mbarrier::complete_tx::bytes [%0], [%1], %2, [%3];"
        :: "r"(dst), "l"(src), "r"(bytes), "r"(mbar) : "memory");
}

__device__ __forceinline__ void ldsm4(uint32_t r[4], uint32_t a) {
    asm volatile("ldmatrix.sync.aligned.m8n8.x4.shared.b16 {%0,%1,%2,%3}, [%4];"
        : "=r"(r[0]), "=r"(r[1]), "=r"(r[2]), "=r"(r[3]) : "r"(a));
}

__device__ __forceinline__ void mma_tf32(float c[4], const uint32_t a[4], const uint32_t b[2]) {
    asm volatile("mma.sync.aligned.m16n8k8.row.col.f32.tf32.tf32.f32 "
        "{%0,%1,%2,%3}, {%4,%5,%6,%7}, {%8,%9}, {%0,%1,%2,%3};"
        : "+f"(c[0]), "+f"(c[1]), "+f"(c[2]), "+f"(c[3])
        : "r"(a[0]), "r"(a[1]), "r"(a[2]), "r"(a[3]), "r"(b[0]), "r"(b[1]));
}

// Fragment base address for ldmatrix.x4 on a [rows][64-float] swizzled tile.
// Physical layout: rowbyte = row*256; 16B chunk c stored at (c ^ (row&7)).
__device__ __forceinline__ uint32_t frag_addr(uint32_t base, uint32_t R, uint32_t C,
                                              uint32_t frow, uint32_t fchunk, uint32_t fsw) {
    return base + (R + frow)*256u + ((((C + fchunk) ^ fsw)) << 4);
}

// ---------------------------------------------------------------------------
// Projection GEMMs (SIMT, tiny): write swizzled GMEM images.
// MODE 0: Q hi/lo images, 128-row chunks.   MODE 1: K hi/lo images, 64-row tiles.
// MODE 2: V^T images, 64-key tiles ([d][key]).
// ---------------------------------------------------------------------------
template <int MODE>
__global__ __launch_bounds__(256) void proj_kernel(
    const float* __restrict__ A, const float* __restrict__ W,
    float* __restrict__ Chi, float* __restrict__ Clo)
{
    __shared__ float sA[64*64];
    __shared__ float sW[64*64];
    int tid = threadIdx.x;
    int rowbase = blockIdx.x * 64;

#pragma unroll
    for (int p = 0; p < 4; p++) {
        int lin = tid + 256*p;
        int r = lin >> 4, c4 = lin & 15;
        float4 av = *(const float4*)(A + (rowbase + r)*64 + c4*4);
        *(float4*)(sA + r*64 + ((c4 ^ (r & 15)) << 2)) = av;
        *(float4*)(sW + r*64 + (c4 << 2)) = *(const float4*)(W + r*64 + c4*4);
    }
    __syncthreads();

    int ty = tid >> 4, tx = tid & 15;
    int r0 = ty*4, c0 = tx*4;
    int rx[4], rb[4];
#pragma unroll
    for (int i = 0; i < 4; i++) { rx[i] = (r0+i) & 15; rb[i] = (r0+i)*64; }

    float acc[4][4] = {};
#pragma unroll
    for (int d4 = 0; d4 < 16; d4++) {
        float a[4][4], bb[4][4];
#pragma unroll
        for (int i = 0; i < 4; i++) {
            float4 t = *(const float4*)(sA + rb[i] + ((d4 ^ rx[i]) << 2));
            a[i][0]=t.x; a[i][1]=t.y; a[i][2]=t.z; a[i][3]=t.w;
        }
#pragma unroll
        for (int k = 0; k < 4; k++) {
            float4 t = *(const float4*)(sW + (d4*4+k)*64 + c0);
            bb[k][0]=t.x; bb[k][1]=t.y; bb[k][2]=t.z; bb[k][3]=t.w;
        }
#pragma unroll
        for (int k = 0; k < 4; k++)
#pragma unroll
            for (int i = 0; i < 4; i++)
#pragma unroll
                for (int j = 0; j < 4; j++)
                    acc[i][j] = fmaf(a[i][k], bb[k][j], acc[i][j]);
    }

#pragma unroll
    for (int i = 0; i < 4; i++) {
        int grow = rowbase + r0 + i;
        if (MODE == 0) {
            int img = grow >> 7, rr = grow & 127;
            uint32_t off = (uint32_t)(rr*64 + ((tx ^ (rr & 7)) << 2));
            float4 h, l;
            h.x = tf32_rna(acc[i][0]); l.x = tf32_rna(acc[i][0]-h.x);
            h.y = tf32_rna(acc[i][1]); l.y = tf32_rna(acc[i][1]-h.y);
            h.z = tf32_rna(acc[i][2]); l.z = tf32_rna(acc[i][2]-h.z);
            h.w = tf32_rna(acc[i][3]); l.w = tf32_rna(acc[i][3]-h.w);
            *(float4*)(Chi + img*8192 + off) = h;
            *(float4*)(Clo + img*8192 + off) = l;
        } else if (MODE == 1) {
            int img = grow >> 6, rr = grow & 63;
            uint32_t off = (uint32_t)(rr*64 + ((tx ^ (rr & 7)) << 2));
            float4 h, l;
            h.x = tf32_rna(acc[i][0]); l.x = tf32_rna(acc[i][0]-h.x);
            h.y = tf32_rna(acc[i][1]); l.y = tf32_rna(acc[i][1]-h.y);
            h.z = tf32_rna(acc[i][2]); l.z = tf32_rna(acc[i][2]-h.z);
            h.w = tf32_rna(acc[i][3]); l.w = tf32_rna(acc[i][3]-h.w);
            *(float4*)(Chi + img*4096 + off) = h;
            *(float4*)(Clo + img*4096 + off) = l;
        } else {
            int img = grow >> 6, kk = grow & 63;
#pragma unroll
            for (int j = 0; j < 4; j++) {
                int e = c0 + j;   // d index = image row
                uint32_t off = (uint32_t)(e*64 + (((kk >> 2) ^ (e & 7)) << 2) + (kk & 3));
                Chi[img*4096 + off] = tf32_rna(acc[i][j]);
            }
        }
    }
}

// ---------------------------------------------------------------------------
// Fused attention via legacy mma.sync (tf32). 128 q x 1024 keys per CTA.
// 8 warps: wm = wid&3 (32-row block), wn = wid>>2 (32-col block).
// ---------------------------------------------------------------------------
#define SM_QH   0u
#define SM_QL   32768u
#define SM_BUF0 65536u
#define SM_BUF1 115712u
#define BUF_KH  0u
#define BUF_KL  16384u
#define BUF_V   32768u
#define BUF_X   49152u
#define SM_P    165888u
#define SM_TOTAL 198656

__global__ __launch_bounds__(256, 1) void attn_mma_kernel(
    const float* __restrict__ xyz1, const float* __restrict__ xyz2,
    const float* __restrict__ gammap)
{
    extern __shared__ char dyn[];
    __shared__ __align__(8) uint64_t mbars[2];
    __shared__ float sDen[2][128];

    uint32_t sb = smem_u32(dyn);
    int tid = threadIdx.x, lane = tid & 31, wid = tid >> 5;
    int wm = wid & 3, wn = wid >> 2;
    int bI = blockIdx.y, nbase = blockIdx.x * 128;
    float g = gammap[0];

    uint32_t mb[2] = { smem_u32(&mbars[0]), smem_u32(&mbars[1]) };
    if (tid == 0) { MBAR_INIT(mb[0], 1); MBAR_INIT(mb[1], 1); }
    __syncthreads();

    if (tid == 0) {
        int img = bI * 16;
        MBAR_EXPECT(mb[0], 32768u*2 + 16384u*3 + 768u);
        bulk_cp(sb + SM_QH, g_qh + (size_t)(bI*32 + blockIdx.x)*8192, 32768, mb[0]);
        bulk_cp(sb + SM_QL, g_ql + (size_t)(bI*32 + blockIdx.x)*8192, 32768, mb[0]);
        bulk_cp(sb + SM_BUF0 + BUF_KH, g_kh + (size_t)img*4096, 16384, mb[0]);
        bulk_cp(sb + SM_BUF0 + BUF_KL, g_kl + (size_t)img*4096, 16384, mb[0]);
        bulk_cp(sb + SM_BUF0 + BUF_V,  g_vT + (size_t)img*4096, 16384, mb[0]);
        bulk_cp(sb + SM_BUF0 + BUF_X,  xyz2 + (size_t)bI*Mm*3, 768, mb[0]);
        MBAR_EXPECT(mb[1], 16384u*3 + 768u);
        bulk_cp(sb + SM_BUF1 + BUF_KH, g_kh + (size_t)(img+1)*4096, 16384, mb[1]);
        bulk_cp(sb + SM_BUF1 + BUF_KL, g_kl + (size_t)(img+1)*4096, 16384, mb[1]);
        bulk_cp(sb + SM_BUF1 + BUF_V,  g_vT + (size_t)(img+1)*4096, 16384, mb[1]);
        bulk_cp(sb + SM_BUF1 + BUF_X,  xyz2 + (size_t)(bI*Mm + 64)*3, 768, mb[1]);
    }

    // ldmatrix per-thread addressing:
    // A-operand (Q, P): matrices = {rows/c0, rows+8/c0, rows/c1, rows+8/c1}
    uint32_t frowA = (uint32_t)((lane & 7) + (((lane >> 3) & 1) << 3));
    uint32_t fchkA = (uint32_t)(lane >> 4);
    // B-operand (K, V): matrices = {rows/c0, rows/c1, rows+8/c0, rows+8/c1}
    uint32_t frowB = (uint32_t)((lane & 7) + ((lane >> 4) << 3));
    uint32_t fchkB = (uint32_t)((lane >> 3) & 1);
    uint32_t fsw   = (uint32_t)(lane & 7);

    // query positions for this thread's 4 rows
    float x1[4][3];
#pragma unroll
    for (int mbi = 0; mbi < 2; mbi++)
#pragma unroll
        for (int h = 0; h < 2; h++) {
            int row = wm*32 + mbi*16 + (lane >> 2) + 8*h;
            const float* xp = xyz1 + ((size_t)bI*Nn + nbase + row)*3;
            x1[mbi*2+h][0] = xp[0]; x1[mbi*2+h][1] = xp[1]; x1[mbi*2+h][2] = xp[2];
        }

    float oacc[8][4] = {};
    float dsum[4] = {};

    for (int t = 0; t < 16; t++) {
        int idx = t & 1;
        uint32_t bufb = sb + (idx ? SM_BUF1 : SM_BUF0);
        MBAR_WAIT(mb[idx], (t >> 1) & 1);

        // ---- MMA1: S = Qh*Kh + Qh*Kl + Ql*Kh ----
        float sacc[8][4] = {};
#pragma unroll
        for (int s = 0; s < 8; s++) {
            uint32_t qh[2][4], ql[2][4], kh[2][4], kl[2][4];
#pragma unroll
            for (int m2 = 0; m2 < 2; m2++) {
                ldsm4(qh[m2], frag_addr(sb + SM_QH, wm*32 + m2*16, 2*s, frowA, fchkA, fsw));
                ldsm4(ql[m2], frag_addr(sb + SM_QL, wm*32 + m2*16, 2*s, frowA, fchkA, fsw));
                ldsm4(kh[m2], frag_addr(bufb + BUF_KH, wn*32 + m2*16, 2*s, frowB, fchkB, fsw));
                ldsm4(kl[m2], frag_addr(bufb + BUF_KL, wn*32 + m2*16, 2*s, frowB, fchkB, fsw));
            }
#pragma unroll
            for (int m2 = 0; m2 < 2; m2++)
#pragma unroll
                for (int fn = 0; fn < 4; fn++) {
                    mma_tf32(sacc[m2*4+fn], qh[m2], &kh[fn>>1][2*(fn&1)]);
                    mma_tf32(sacc[m2*4+fn], qh[m2], &kl[fn>>1][2*(fn&1)]);
                    mma_tf32(sacc[m2*4+fn], ql[m2], &kh[fn>>1][2*(fn&1)]);
                }
        }

        // ---- epilogue: S -> P (RBF-weighted exp), dsum ----
        const float* px2 = (const float*)(dyn + (idx ? SM_BUF1 : SM_BUF0) + BUF_X);
#pragma unroll
        for (int m2 = 0; m2 < 2; m2++)
#pragma unroll
            for (int fn = 0; fn < 4; fn++) {
                int colb = wn*32 + fn*8 + 2*(lane & 3);
                float c0x = px2[colb*3+0], c0y = px2[colb*3+1], c0z = px2[colb*3+2];
                float c1x = px2[colb*3+3], c1y = px2[colb*3+4], c1z = px2[colb*3+5];
#pragma unroll
                for (int h = 0; h < 2; h++) {
                    float s0 = sacc[m2*4+fn][2*h+0];
                    float s1 = sacc[m2*4+fn][2*h+1];
                    float e20 = __expf(s0);
                    float e21 = __expf(s1);
                    dsum[m2*2+h] += e20 + e21;
                    float ax = x1[m2*2+h][0], ay = x1[m2*2+h][1], az = x1[m2*2+h][2];
                    float dx0 = ax-c0x, dy0 = ay-c0y, dz0 = az-c0z;
                    float dx1 = ax-c1x, dy1 = ay-c1y, dz1 = az-c1z;
                    float dd0 = fmaf(dx0,dx0, fmaf(dy0,dy0, dz0*dz0));
                    float dd1 = fmaf(dx1,dx1, fmaf(dy1,dy1, dz1*dz1));
                    float e10 = __expf(-g*dd0);
                    float e11 = __expf(-g*dd1);
                    float2 pv;
                    pv.x = tf32_rna((e10 > 0.05f) ? e10*e20 : 0.0f);
                    pv.y = tf32_rna((e11 > 0.05f) ? e11*e21 : 0.0f);
                    int row = wm*32 + m2*16 + (lane >> 2) + 8*h;
                    uint32_t pa = SM_P + (uint32_t)row*256u
                                + ((((uint32_t)colb >> 2) ^ (uint32_t)(lane >> 2)) << 4)
                                + ((uint32_t)colb & 3u)*4u;
                    *(float2*)(dyn + pa) = pv;
                }
            }
        __syncthreads();

        // ---- MMA2: O += P * V ----
#pragma unroll
        for (int s = 0; s < 8; s++) {
            uint32_t pa[2][4], vb[2][4];
#pragma unroll
            for (int m2 = 0; m2 < 2; m2++) {
                ldsm4(pa[m2], frag_addr(sb + SM_P, wm*32 + m2*16, 2*s, frowA, fchkA, fsw));
                ldsm4(vb[m2], frag_addr(bufb + BUF_V, wn*32 + m2*16, 2*s, frowB, fchkB, fsw));
            }
#pragma unroll
            for (int m2 = 0; m2 < 2; m2++)
#pragma unroll
                for (int fn = 0; fn < 4; fn++)
                    mma_tf32(oacc[m2*4+fn], pa[m2], &vb[fn>>1][2*(fn&1)]);
        }
        __syncthreads();

        // prefetch tile t+2 into the buffer just freed
        if (t < 14 && tid == 0) {
            int img = bI*16 + t + 2;
            uint32_t dstb = sb + (idx ? SM_BUF1 : SM_BUF0);
            MBAR_EXPECT(mb[idx], 16384u*3 + 768u);
            bulk_cp(dstb + BUF_KH, g_kh + (size_t)img*4096, 16384, mb[idx]);
            bulk_cp(dstb + BUF_KL, g_kl + (size_t)img*4096, 16384, mb[idx]);
            bulk_cp(dstb + BUF_V,  g_vT + (size_t)img*4096, 16384, mb[idx]);
            bulk_cp(dstb + BUF_X,  xyz2 + (size_t)(bI*Mm + (t+2)*64)*3, 768, mb[idx]);
        }
    }

    // ---- denominator reduction ----
#pragma unroll
    for (int off = 1; off < 4; off <<= 1)
#pragma unroll
        for (int i = 0; i < 4; i++)
            dsum[i] += __shfl_xor_sync(0xFFFFFFFFu, dsum[i], off);
    if ((lane & 3) == 0) {
#pragma unroll
        for (int m2 = 0; m2 < 2; m2++)
#pragma unroll
            for (int h = 0; h < 2; h++)
                sDen[wn][wm*32 + m2*16 + (lane >> 2) + 8*h] = dsum[m2*2+h];
    }
    __syncthreads();

    float inv[4];
#pragma unroll
    for (int m2 = 0; m2 < 2; m2++)
#pragma unroll
        for (int h = 0; h < 2; h++) {
            int row = wm*32 + m2*16 + (lane >> 2) + 8*h;
            inv[m2*2+h] = 1.0f / (sDen[0][row] + sDen[1][row]);
        }

    // ---- normalize + store ----
#pragma unroll
    for (int m2 = 0; m2 < 2; m2++)
#pragma unroll
        for (int fn = 0; fn < 4; fn++) {
            int colb = wn*32 + fn*8 + 2*(lane & 3);
#pragma unroll
            for (int h = 0; h < 2; h++) {
                int row = wm*32 + m2*16 + (lane >> 2) + 8*h;
                float iv = inv[m2*2+h];
                float2 o;
                o.x = oacc[m2*4+fn][2*h+0] * iv;
                o.y = oacc[m2*4+fn][2*h+1] * iv;
                *(float2*)(g_kern + ((size_t)bI*Nn + nbase + row)*64 + colb) = o;
            }
        }
}

// ---------------------------------------------------------------------------
// Output MLP: out = relu(concat(points1, kern) @ Wo + bo)
// ---------------------------------------------------------------------------
__global__ __launch_bounds__(256) void mlp_kernel(
    const float* __restrict__ p1, const float* __restrict__ Wo,
    const float* __restrict__ bo, float* __restrict__ out)
{
    __shared__ float sA[64*64];
    __shared__ float sB[64*128];
    int tid = threadIdx.x;
    int rowbase = blockIdx.x * 64;
    int ty = tid >> 4, tx = tid & 15;
    int r0 = ty*4, c0 = tx*4;
    int rx[4], rb[4];
#pragma unroll
    for (int i = 0; i < 4; i++) { rx[i] = (r0+i) & 15; rb[i] = (r0+i)*64; }

    float acc[4][8] = {};
#pragma unroll 1
    for (int ch = 0; ch < 2; ch++) {
        const float* Asrc = ch ? (const float*)g_kern : p1;
        __syncthreads();
#pragma unroll
        for (int p = 0; p < 4; p++) {
            int lin = tid + 256*p;
            int r = lin >> 4, c4 = lin & 15;
            float4 t = *(const float4*)(Asrc + (rowbase + r)*64 + c4*4);
            *(float4*)(sA + r*64 + ((c4 ^ (r & 15)) << 2)) = t;
        }
#pragma unroll
        for (int p = 0; p < 8; p++) {
            int lin = tid + 256*p;
            int r = lin >> 5, c4 = lin & 31;
            *(float4*)(sB + r*128 + c4*4) = *(const float4*)(Wo + (ch*64 + r)*128 + c4*4);
        }
        __syncthreads();

#pragma unroll
        for (int d4 = 0; d4 < 16; d4++) {
            float a[4][4], b1[4][4], b2[4][4];
#pragma unroll
            for (int i = 0; i < 4; i++) {
                float4 t = *(const float4*)(sA + rb[i] + ((d4 ^ rx[i]) << 2));
                a[i][0]=t.x; a[i][1]=t.y; a[i][2]=t.z; a[i][3]=t.w;
            }
#pragma unroll
            for (int k = 0; k < 4; k++) {
                float4 t = *(const float4*)(sB + (d4*4+k)*128 + c0);
                b1[k][0]=t.x; b1[k][1]=t.y; b1[k][2]=t.z; b1[k][3]=t.w;
                float4 u = *(const float4*)(sB + (d4*4+k)*128 + 64 + c0);
                b2[k][0]=u.x; b2[k][1]=u.y; b2[k][2]=u.z; b2[k][3]=u.w;
            }
#pragma unroll
            for (int k = 0; k < 4; k++)
#pragma unroll
                for (int i = 0; i < 4; i++)
#pragma unroll
                    for (int j = 0; j < 4; j++) {
                        acc[i][j]   = fmaf(a[i][k], b1[k][j], acc[i][j]);
                        acc[i][4+j] = fmaf(a[i][k], b2[k][j], acc[i][4+j]);
                    }
        }
    }

    float bov[8];
#pragma unroll
    for (int j = 0; j < 4; j++) { bov[j] = bo[c0+j]; bov[4+j] = bo[64+c0+j]; }
#pragma unroll
    for (int i = 0; i < 4; i++) {
        int grow = rowbase + r0 + i;
        float4 o1, o2;
        o1.x = fmaxf(acc[i][0]+bov[0], 0.0f);
        o1.y = fmaxf(acc[i][1]+bov[1], 0.0f);
        o1.z = fmaxf(acc[i][2]+bov[2], 0.0f);
        o1.w = fmaxf(acc[i][3]+bov[3], 0.0f);
        o2.x = fmaxf(acc[i][4]+bov[4], 0.0f);
        o2.y = fmaxf(acc[i][5]+bov[5], 0.0f);
        o2.z = fmaxf(acc[i][6]+bov[6], 0.0f);
        o2.w = fmaxf(acc[i][7]+bov[7], 0.0f);
        *(float4*)(out + grow*128 + c0) = o1;
        *(float4*)(out + grow*128 + 64 + c0) = o2;
    }
}

// ---------------------------------------------------------------------------
extern "C" void kernel_launch(void* const* d_in, const int* in_sizes, int n_in,
                              void* d_out, int out_size)
{
    const float* xyz1 = (const float*)d_in[0];
    const float* xyz2 = (const float*)d_in[1];
    const float* p1   = (const float*)d_in[2];
    const float* p2   = (const float*)d_in[3];
    const float* Wq   = (const float*)d_in[4];
    const float* Wk   = (const float*)d_in[5];
    const float* Wv   = (const float*)d_in[6];
    const float* gm   = (const float*)d_in[7];
    const float* Wo   = (const float*)d_in[8];
    const float* bo   = (const float*)d_in[9];
    float* out = (float*)d_out;

    float *dqh, *dql, *dkh, *dkl, *dvT;
    cudaGetSymbolAddress((void**)&dqh, g_qh);
    cudaGetSymbolAddress((void**)&dql, g_ql);
    cudaGetSymbolAddress((void**)&dkh, g_kh);
    cudaGetSymbolAddress((void**)&dkl, g_kl);
    cudaGetSymbolAddress((void**)&dvT, g_vT);

    proj_kernel<0><<<(Bb*Nn)/64, 256>>>(p1, Wq, dqh, dql);
    proj_kernel<1><<<(Bb*Mm)/64, 256>>>(p2, Wk, dkh, dkl);
    proj_kernel<2><<<(Bb*Mm)/64, 256>>>(p2, Wv, dvT, nullptr);

    cudaFuncSetAttribute(attn_mma_kernel, cudaFuncAttributeMaxDynamicSharedMemorySize, SM_TOTAL);
    attn_mma_kernel<<<dim3(Nn/128, Bb), 256, SM_TOTAL>>>(xyz1, xyz2, gm);

    mlp_kernel<<<(Bb*Nn)/64, 256>>>(p1, Wo, bo, out);
}

// round 5
// speedup vs baseline: 2.2831x; 1.2006x over previous
#include <cuda_runtime.h>
#include <cuda_fp16.h>
#include <cstdint>

#define Bb 8
#define Nn 4096
#define Mm 1024

// ---------------------------------------------------------------------------
// Scratch (device globals) — pre-swizzled images for flat bulk copies
// ---------------------------------------------------------------------------
__device__ __half g_qh[Bb*Nn*64];   // Q hi fp16, per-64-row-chunk swizzled images
__device__ __half g_ql[Bb*Nn*64];   // Q lo fp16
__device__ __half g_kh[Bb*Mm*64];   // K hi fp16, per-64-key-tile images ([key][d])
__device__ __half g_kl[Bb*Mm*64];   // K lo fp16
__device__ float  g_vT[Bb*Mm*64];   // V^T tf32, per-64-key-tile images ([d][key])
__device__ float  g_kern[Bb*Nn*64]; // attention output [b][n][d]

// ---------------------------------------------------------------------------
// Helpers
// ---------------------------------------------------------------------------
__device__ __forceinline__ uint32_t smem_u32(const void* p) {
    uint32_t a;
    asm("{ .reg .u64 t; cvta.to.shared.u64 t, %1; cvt.u32.u64 %0, t; }" : "=r"(a) : "l"(p));
    return a;
}
__device__ __forceinline__ float tf32_rna(float x) {
    uint32_t u;
    asm("cvt.rna.tf32.f32 %0, %1;" : "=r"(u) : "f"(x));
    return __uint_as_float(u);
}

#define MBAR_INIT(a, c) asm volatile("mbarrier.init.shared.b64 [%0], %1;" :: "r"(a), "r"((uint32_t)(c)) : "memory")
#define MBAR_EXPECT(a, b) asm volatile("mbarrier.arrive.expect_tx.shared.b64 _, [%0], %1;" :: "r"(a), "r"((uint32_t)(b)) : "memory")
#define MBAR_WAIT(a, ph) do { \
    asm volatile("{ .reg .pred P1; WL_%=: mbarrier.try_wait.parity.acquire.cta.shared::cta.b64 P1, [%0], %1, 0x989680; @P1 bra.uni WD_%=; bra.uni WL_%=; WD_%=: }" \
        :: "r"(a), "r"((uint32_t)(ph)) : "memory"); } while (0)

__device__ __forceinline__ void bulk_cp(uint32_t dst, const void* src, uint32_t bytes, uint32_t mbar) {
    asm volatile("cp.async.bulk.shared::cta.global.mbarrier::complete_tx::bytes [%0], [%1], %2, [%3];"
        :: "r"(dst), "l"(src), "r"(bytes), "r"(mbar) : "memory");
}

__device__ __forceinline__ void ldsm4(uint32_t r[4], uint32_t a) {
    asm volatile("ldmatrix.sync.aligned.m8n8.x4.shared.b16 {%0,%1,%2,%3}, [%4];"
        : "=r"(r[0]), "=r"(r[1]), "=r"(r[2]), "=r"(r[3]) : "r"(a));
}

__device__ __forceinline__ void mma_tf32(float c[4], const uint32_t a[4], const uint32_t b[2]) {
    asm volatile("mma.sync.aligned.m16n8k8.row.col.f32.tf32.tf32.f32 "
        "{%0,%1,%2,%3}, {%4,%5,%6,%7}, {%8,%9}, {%0,%1,%2,%3};"
        : "+f"(c[0]), "+f"(c[1]), "+f"(c[2]), "+f"(c[3])
        : "r"(a[0]), "r"(a[1]), "r"(a[2]), "r"(a[3]), "r"(b[0]), "r"(b[1]));
}
__device__ __forceinline__ void mma_f16(float c[4], const uint32_t a[4], const uint32_t b[2]) {
    asm volatile("mma.sync.aligned.m16n8k16.row.col.f32.f16.f16.f32 "
        "{%0,%1,%2,%3}, {%4,%5,%6,%7}, {%8,%9}, {%0,%1,%2,%3};"
        : "+f"(c[0]), "+f"(c[1]), "+f"(c[2]), "+f"(c[3])
        : "r"(a[0]), "r"(a[1]), "r"(a[2]), "r"(a[3]), "r"(b[0]), "r"(b[1]));
}

// ---------------------------------------------------------------------------
// Projection GEMMs (SIMT): write swizzled GMEM images.
// MODE 0: Q fp16 hi/lo, 64-row-chunk images (128B rows, 8-chunk xor swizzle)
// MODE 1: K fp16 hi/lo, 64-key-tile images
// MODE 2: V^T tf32 images (256B rows, 16-chunk xor swizzle)
// ---------------------------------------------------------------------------
template <int MODE>
__global__ __launch_bounds__(256) void proj_kernel(
    const float* __restrict__ A, const float* __restrict__ W,
    void* __restrict__ Cout_hi, void* __restrict__ Cout_lo)
{
    __shared__ float sA[64*64];
    __shared__ float sW[64*64];
    int tid = threadIdx.x;
    int rowbase = blockIdx.x * 64;

#pragma unroll
    for (int p = 0; p < 4; p++) {
        int lin = tid + 256*p;
        int r = lin >> 4, c4 = lin & 15;
        float4 av = *(const float4*)(A + (rowbase + r)*64 + c4*4);
        *(float4*)(sA + r*64 + ((c4 ^ (r & 15)) << 2)) = av;
        *(float4*)(sW + r*64 + (c4 << 2)) = *(const float4*)(W + r*64 + c4*4);
    }
    __syncthreads();

    int ty = tid >> 4, tx = tid & 15;
    int r0 = ty*4, c0 = tx*4;
    int rx[4], rb[4];
#pragma unroll
    for (int i = 0; i < 4; i++) { rx[i] = (r0+i) & 15; rb[i] = (r0+i)*64; }

    float acc[4][4] = {};
#pragma unroll
    for (int d4 = 0; d4 < 16; d4++) {
        float a[4][4], bb[4][4];
#pragma unroll
        for (int i = 0; i < 4; i++) {
            float4 t = *(const float4*)(sA + rb[i] + ((d4 ^ rx[i]) << 2));
            a[i][0]=t.x; a[i][1]=t.y; a[i][2]=t.z; a[i][3]=t.w;
        }
#pragma unroll
        for (int k = 0; k < 4; k++) {
            float4 t = *(const float4*)(sW + (d4*4+k)*64 + c0);
            bb[k][0]=t.x; bb[k][1]=t.y; bb[k][2]=t.z; bb[k][3]=t.w;
        }
#pragma unroll
        for (int k = 0; k < 4; k++)
#pragma unroll
            for (int i = 0; i < 4; i++)
#pragma unroll
                for (int j = 0; j < 4; j++)
                    acc[i][j] = fmaf(a[i][k], bb[k][j], acc[i][j]);
    }

#pragma unroll
    for (int i = 0; i < 4; i++) {
        int grow = rowbase + r0 + i;
        if (MODE <= 1) {
            // fp16 hi/lo image: 64 rows x 64 halfs (128B rows), chunk xor swizzle
            int img = grow >> 6, rr = grow & 63;
            uint32_t swc = ((uint32_t)(c0 >> 3)) ^ (uint32_t)(rr & 7);
            uint32_t hoff = (uint32_t)rr*64u + swc*8u + (uint32_t)(c0 & 7);
            __half h[4], l[4];
#pragma unroll
            for (int j = 0; j < 4; j++) {
                h[j] = __float2half_rn(acc[i][j]);
                l[j] = __float2half_rn(acc[i][j] - __half2float(h[j]));
            }
            __half* ph = (__half*)Cout_hi + (size_t)img*4096 + hoff;
            __half* pl = (__half*)Cout_lo + (size_t)img*4096 + hoff;
            *(__half2*)(ph)     = __halves2half2(h[0], h[1]);
            *(__half2*)(ph + 2) = __halves2half2(h[2], h[3]);
            *(__half2*)(pl)     = __halves2half2(l[0], l[1]);
            *(__half2*)(pl + 2) = __halves2half2(l[2], l[3]);
        } else {
            // V^T tf32 image: row = d, col = key, 256B rows
            int img = grow >> 6, kk = grow & 63;
#pragma unroll
            for (int j = 0; j < 4; j++) {
                int e = c0 + j;
                uint32_t off = (uint32_t)(e*64 + (((kk >> 2) ^ (e & 7)) << 2) + (kk & 3));
                ((float*)Cout_hi)[img*4096 + off] = tf32_rna(acc[i][j]);
            }
        }
    }
}

// ---------------------------------------------------------------------------
// Fused attention: 64 queries x 1024 keys per CTA, 8 warps, 2 CTAs/SM.
// MMA1 (S=QK^T): fp16 2-split, 3 passes of m16n8k16. MMA2 (PV): tf32.
// Q fragments preloaded to registers once.
// ---------------------------------------------------------------------------
#define SM_P     0u          // 16KB: P tf32 tile; staging for QH(0)/QL(8192) at start
#define SM_BUF0  16384u
#define SM_BUF1  50176u      // buf stride 33792
#define BUF_KH   0u          // 8KB fp16
#define BUF_KL   8192u       // 8KB fp16
#define BUF_V    16384u      // 16KB tf32
#define BUF_X    32768u      // 768B xyz2 tile
#define BUF_BYTES 33536u
#define SM_TOTAL 83968

__global__ __launch_bounds__(256, 2) void attn_mma_kernel(
    const float* __restrict__ xyz1, const float* __restrict__ xyz2,
    const float* __restrict__ gammap)
{
    extern __shared__ char dyn[];
    __shared__ __align__(8) uint64_t mbars[2];
    __shared__ float sDen[2][64];

    uint32_t sb = smem_u32(dyn);
    int tid = threadIdx.x, lane = tid & 31, wid = tid >> 5;
    int wm = wid & 3, wn = wid >> 2;
    int bI = blockIdx.y, nbase = blockIdx.x * 64;
    float g = gammap[0];

    uint32_t mb[2] = { smem_u32(&mbars[0]), smem_u32(&mbars[1]) };
    if (tid == 0) { MBAR_INIT(mb[0], 1); MBAR_INIT(mb[1], 1); }
    __syncthreads();

    if (tid == 0) {
        int img = bI * 16;
        int qimg = bI*64 + blockIdx.x;
        MBAR_EXPECT(mb[0], 8192u*2 + BUF_BYTES);
        bulk_cp(sb + SM_P,        g_qh + (size_t)qimg*4096, 8192, mb[0]);
        bulk_cp(sb + SM_P + 8192, g_ql + (size_t)qimg*4096, 8192, mb[0]);
        bulk_cp(sb + SM_BUF0 + BUF_KH, g_kh + (size_t)img*4096, 8192, mb[0]);
        bulk_cp(sb + SM_BUF0 + BUF_KL, g_kl + (size_t)img*4096, 8192, mb[0]);
        bulk_cp(sb + SM_BUF0 + BUF_V,  g_vT + (size_t)img*4096, 16384, mb[0]);
        bulk_cp(sb + SM_BUF0 + BUF_X,  xyz2 + (size_t)bI*Mm*3, 768, mb[0]);
        MBAR_EXPECT(mb[1], BUF_BYTES);
        bulk_cp(sb + SM_BUF1 + BUF_KH, g_kh + (size_t)(img+1)*4096, 8192, mb[1]);
        bulk_cp(sb + SM_BUF1 + BUF_KL, g_kl + (size_t)(img+1)*4096, 8192, mb[1]);
        bulk_cp(sb + SM_BUF1 + BUF_V,  g_vT + (size_t)(img+1)*4096, 16384, mb[1]);
        bulk_cp(sb + SM_BUF1 + BUF_X,  xyz2 + (size_t)(bI*Mm + 64)*3, 768, mb[1]);
    }

    // fragment addressing (A map == tf32 A map; B map == tf32 B map)
    uint32_t frowA = (uint32_t)((lane & 7) + (((lane >> 3) & 1) << 3));
    uint32_t fchkA = (uint32_t)(lane >> 4);
    uint32_t frowB = (uint32_t)((lane & 7) + ((lane >> 4) << 3));
    uint32_t fchkB = (uint32_t)((lane >> 3) & 1);
    uint32_t fsw   = (uint32_t)(lane & 7);

    // query positions (2 rows per thread)
    float x1[2][3];
#pragma unroll
    for (int h = 0; h < 2; h++) {
        int row = wm*16 + (lane >> 2) + 8*h;
        const float* xp = xyz1 + ((size_t)bI*Nn + nbase + row)*3;
        x1[h][0] = xp[0]; x1[h][1] = xp[1]; x1[h][2] = xp[2];
    }

    // ---- preload Q fragments (whole kernel) ----
    MBAR_WAIT(mb[0], 0);
    uint32_t qh[4][4], ql[4][4];
    {
        uint32_t qrow = (uint32_t)(wm*16) + frowA;
#pragma unroll
        for (int s = 0; s < 4; s++) {
            uint32_t chunk = ((uint32_t)(2*s) + fchkA) ^ fsw;
            ldsm4(qh[s], sb + SM_P +        qrow*128u + (chunk << 4));
            ldsm4(ql[s], sb + SM_P + 8192u + qrow*128u + (chunk << 4));
        }
    }
    __syncthreads();   // Q staging read by all warps before P overwrites it

    float oacc[4][4] = {};
    float dsum[2] = {};

    for (int t = 0; t < 16; t++) {
        int idx = t & 1;
        uint32_t bufb = sb + (idx ? SM_BUF1 : SM_BUF0);
        if (t) MBAR_WAIT(mb[idx], (t >> 1) & 1);

        // ---- MMA1: S = Qh*Kh + Qh*Kl + Ql*Kh (fp16, K=64 in 4 k16 steps) ----
        float sacc[4][4] = {};
        uint32_t krow0 = (uint32_t)(wn*32) + frowB;
#pragma unroll
        for (int s = 0; s < 4; s++) {
            uint32_t chunk = ((uint32_t)(2*s) + fchkB) ^ fsw;
            uint32_t kh2[2][4], kl2[2][4];
            ldsm4(kh2[0], bufb + BUF_KH + krow0*128u + (chunk << 4));
            ldsm4(kh2[1], bufb + BUF_KH + (krow0 + 16u)*128u + (chunk << 4));
            ldsm4(kl2[0], bufb + BUF_KL + krow0*128u + (chunk << 4));
            ldsm4(kl2[1], bufb + BUF_KL + (krow0 + 16u)*128u + (chunk << 4));
#pragma unroll
            for (int fn = 0; fn < 4; fn++) {
                mma_f16(sacc[fn], qh[s], &kh2[fn>>1][2*(fn&1)]);
                mma_f16(sacc[fn], qh[s], &kl2[fn>>1][2*(fn&1)]);
                mma_f16(sacc[fn], ql[s], &kh2[fn>>1][2*(fn&1)]);
            }
        }

        // ---- epilogue: S -> P (RBF-weighted exp), dsum ----
        const float* px2 = (const float*)(dyn + (idx ? SM_BUF1 : SM_BUF0) + BUF_X);
#pragma unroll
        for (int fn = 0; fn < 4; fn++) {
            int colb = wn*32 + fn*8 + 2*(lane & 3);
            float c0x = px2[colb*3+0], c0y = px2[colb*3+1], c0z = px2[colb*3+2];
            float c1x = px2[colb*3+3], c1y = px2[colb*3+4], c1z = px2[colb*3+5];
#pragma unroll
            for (int h = 0; h < 2; h++) {
                float s0 = sacc[fn][2*h+0];
                float s1 = sacc[fn][2*h+1];
                float e20 = __expf(s0);
                float e21 = __expf(s1);
                dsum[h] += e20 + e21;
                float ax = x1[h][0], ay = x1[h][1], az = x1[h][2];
                float dx0 = ax-c0x, dy0 = ay-c0y, dz0 = az-c0z;
                float dx1 = ax-c1x, dy1 = ay-c1y, dz1 = az-c1z;
                float dd0 = fmaf(dx0,dx0, fmaf(dy0,dy0, dz0*dz0));
                float dd1 = fmaf(dx1,dx1, fmaf(dy1,dy1, dz1*dz1));
                float e10 = __expf(-g*dd0);
                float e11 = __expf(-g*dd1);
                float2 pv;
                pv.x = tf32_rna((e10 > 0.05f) ? e10*e20 : 0.0f);
                pv.y = tf32_rna((e11 > 0.05f) ? e11*e21 : 0.0f);
                int row = wm*16 + (lane >> 2) + 8*h;
                uint32_t pa = SM_P + (uint32_t)row*256u
                            + ((((uint32_t)colb >> 2) ^ (uint32_t)(lane >> 2)) << 4)
                            + ((uint32_t)colb & 3u)*4u;
                *(float2*)(dyn + pa) = pv;
            }
        }
        __syncthreads();

        // ---- MMA2: O += P * V (tf32, 8 k8 steps) ----
        uint32_t prow = (uint32_t)(wm*16) + frowA;
        uint32_t vrow0 = (uint32_t)(wn*32) + frowB;
#pragma unroll
        for (int s = 0; s < 8; s++) {
            uint32_t chunkA = ((uint32_t)(2*s) + fchkA) ^ fsw;
            uint32_t chunkB = ((uint32_t)(2*s) + fchkB) ^ fsw;
            uint32_t pf[4], v2[2][4];
            ldsm4(pf, sb + SM_P + prow*256u + (chunkA << 4));
            ldsm4(v2[0], bufb + BUF_V + vrow0*256u + (chunkB << 4));
            ldsm4(v2[1], bufb + BUF_V + (vrow0 + 16u)*256u + (chunkB << 4));
#pragma unroll
            for (int fn = 0; fn < 4; fn++)
                mma_tf32(oacc[fn], pf, &v2[fn>>1][2*(fn&1)]);
        }
        __syncthreads();

        // prefetch tile t+2 into the buffer just freed
        if (t < 14 && tid == 0) {
            int img = bI*16 + t + 2;
            uint32_t dstb = sb + (idx ? SM_BUF1 : SM_BUF0);
            MBAR_EXPECT(mb[idx], BUF_BYTES);
            bulk_cp(dstb + BUF_KH, g_kh + (size_t)img*4096, 8192, mb[idx]);
            bulk_cp(dstb + BUF_KL, g_kl + (size_t)img*4096, 8192, mb[idx]);
            bulk_cp(dstb + BUF_V,  g_vT + (size_t)img*4096, 16384, mb[idx]);
            bulk_cp(dstb + BUF_X,  xyz2 + (size_t)(bI*Mm + (t+2)*64)*3, 768, mb[idx]);
        }
    }

    // ---- denominator reduction (4 lanes share each row) ----
#pragma unroll
    for (int off = 1; off < 4; off <<= 1)
#pragma unroll
        for (int h = 0; h < 2; h++)
            dsum[h] += __shfl_xor_sync(0xFFFFFFFFu, dsum[h], off);
    if ((lane & 3) == 0)
#pragma unroll
        for (int h = 0; h < 2; h++)
            sDen[wn][wm*16 + (lane >> 2) + 8*h] = dsum[h];
    __syncthreads();

    float inv[2];
#pragma unroll
    for (int h = 0; h < 2; h++) {
        int row = wm*16 + (lane >> 2) + 8*h;
        inv[h] = 1.0f / (sDen[0][row] + sDen[1][row]);
    }

    // ---- normalize + store ----
#pragma unroll
    for (int fn = 0; fn < 4; fn++) {
        int colb = wn*32 + fn*8 + 2*(lane & 3);
#pragma unroll
        for (int h = 0; h < 2; h++) {
            int row = wm*16 + (lane >> 2) + 8*h;
            float2 o;
            o.x = oacc[fn][2*h+0] * inv[h];
            o.y = oacc[fn][2*h+1] * inv[h];
            *(float2*)(g_kern + ((size_t)bI*Nn + nbase + row)*64 + colb) = o;
        }
    }
}

// ---------------------------------------------------------------------------
// Output MLP: out = relu(concat(points1, kern) @ Wo + bo)
// ---------------------------------------------------------------------------
__global__ __launch_bounds__(256) void mlp_kernel(
    const float* __restrict__ p1, const float* __restrict__ Wo,
    const float* __restrict__ bo, float* __restrict__ out)
{
    __shared__ float sA[64*64];
    __shared__ float sB[64*128];
    int tid = threadIdx.x;
    int rowbase = blockIdx.x * 64;
    int ty = tid >> 4, tx = tid & 15;
    int r0 = ty*4, c0 = tx*4;
    int rx[4], rb[4];
#pragma unroll
    for (int i = 0; i < 4; i++) { rx[i] = (r0+i) & 15; rb[i] = (r0+i)*64; }

    float acc[4][8] = {};
#pragma unroll 1
    for (int ch = 0; ch < 2; ch++) {
        const float* Asrc = ch ? (const float*)g_kern : p1;
        __syncthreads();
#pragma unroll
        for (int p = 0; p < 4; p++) {
            int lin = tid + 256*p;
            int r = lin >> 4, c4 = lin & 15;
            float4 t = *(const float4*)(Asrc + (rowbase + r)*64 + c4*4);
            *(float4*)(sA + r*64 + ((c4 ^ (r & 15)) << 2)) = t;
        }
#pragma unroll
        for (int p = 0; p < 8; p++) {
            int lin = tid + 256*p;
            int r = lin >> 5, c4 = lin & 31;
            *(float4*)(sB + r*128 + c4*4) = *(const float4*)(Wo + (ch*64 + r)*128 + c4*4);
        }
        __syncthreads();

#pragma unroll
        for (int d4 = 0; d4 < 16; d4++) {
            float a[4][4], b1[4][4], b2[4][4];
#pragma unroll
            for (int i = 0; i < 4; i++) {
                float4 t = *(const float4*)(sA + rb[i] + ((d4 ^ rx[i]) << 2));
                a[i][0]=t.x; a[i][1]=t.y; a[i][2]=t.z; a[i][3]=t.w;
            }
#pragma unroll
            for (int k = 0; k < 4; k++) {
                float4 t = *(const float4*)(sB + (d4*4+k)*128 + c0);
                b1[k][0]=t.x; b1[k][1]=t.y; b1[k][2]=t.z; b1[k][3]=t.w;
                float4 u = *(const float4*)(sB + (d4*4+k)*128 + 64 + c0);
                b2[k][0]=u.x; b2[k][1]=u.y; b2[k][2]=u.z; b2[k][3]=u.w;
            }
#pragma unroll
            for (int k = 0; k < 4; k++)
#pragma unroll
                for (int i = 0; i < 4; i++)
#pragma unroll
                    for (int j = 0; j < 4; j++) {
                        acc[i][j]   = fmaf(a[i][k], b1[k][j], acc[i][j]);
                        acc[i][4+j] = fmaf(a[i][k], b2[k][j], acc[i][4+j]);
                    }
        }
    }

    float bov[8];
#pragma unroll
    for (int j = 0; j < 4; j++) { bov[j] = bo[c0+j]; bov[4+j] = bo[64+c0+j]; }
#pragma unroll
    for (int i = 0; i < 4; i++) {
        int grow = rowbase + r0 + i;
        float4 o1, o2;
        o1.x = fmaxf(acc[i][0]+bov[0], 0.0f);
        o1.y = fmaxf(acc[i][1]+bov[1], 0.0f);
        o1.z = fmaxf(acc[i][2]+bov[2], 0.0f);
        o1.w = fmaxf(acc[i][3]+bov[3], 0.0f);
        o2.x = fmaxf(acc[i][4]+bov[4], 0.0f);
        o2.y = fmaxf(acc[i][5]+bov[5], 0.0f);
        o2.z = fmaxf(acc[i][6]+bov[6], 0.0f);
        o2.w = fmaxf(acc[i][7]+bov[7], 0.0f);
        *(float4*)(out + grow*128 + c0) = o1;
        *(float4*)(out + grow*128 + 64 + c0) = o2;
    }
}

// ---------------------------------------------------------------------------
extern "C" void kernel_launch(void* const* d_in, const int* in_sizes, int n_in,
                              void* d_out, int out_size)
{
    const float* xyz1 = (const float*)d_in[0];
    const float* xyz2 = (const float*)d_in[1];
    const float* p1   = (const float*)d_in[2];
    const float* p2   = (const float*)d_in[3];
    const float* Wq   = (const float*)d_in[4];
    const float* Wk   = (const float*)d_in[5];
    const float* Wv   = (const float*)d_in[6];
    const float* gm   = (const float*)d_in[7];
    const float* Wo   = (const float*)d_in[8];
    const float* bo   = (const float*)d_in[9];
    float* out = (float*)d_out;

    void *dqh, *dql, *dkh, *dkl, *dvT;
    cudaGetSymbolAddress(&dqh, g_qh);
    cudaGetSymbolAddress(&dql, g_ql);
    cudaGetSymbolAddress(&dkh, g_kh);
    cudaGetSymbolAddress(&dkl, g_kl);
    cudaGetSymbolAddress(&dvT, g_vT);

    proj_kernel<0><<<(Bb*Nn)/64, 256>>>(p1, Wq, dqh, dql);
    proj_kernel<1><<<(Bb*Mm)/64, 256>>>(p2, Wk, dkh, dkl);
    proj_kernel<2><<<(Bb*Mm)/64, 256>>>(p2, Wv, dvT, nullptr);

    cudaFuncSetAttribute(attn_mma_kernel, cudaFuncAttributeMaxDynamicSharedMemorySize, SM_TOTAL);
    attn_mma_kernel<<<dim3(Nn/64, Bb), 256, SM_TOTAL>>>(xyz1, xyz2, gm);

    mlp_kernel<<<(Bb*Nn)/64, 256>>>(p1, Wo, bo, out);
}